// round 1
// baseline (speedup 1.0000x reference)
#include <cuda_runtime.h>
#include <math.h>

#define Bb   4
#define Dd   64
#define Hh   4
#define DHd  16
#define Nn   2304
#define BHh  16   // B*heads

// ---------------- scratch (device globals; no allocation allowed) ----------
__device__ float d_q[BHh * Nn * DHd];      // q[bh][n][k]
__device__ float d_qn[BHh * Nn];           // ||q||^2 per (bh,n)
__device__ float d_A[Hh * Dd * Dd];        // A_h = WqR WqR^T / 4
__device__ float d_f[BHh * Nn * Dd];       // f = softmax(P) @ x_r
__device__ float d_g[BHh * Nn * Dd];       // g = f @ A
__device__ float d_v[BHh * DHd * Nn];      // v[bh][k][vc]
__device__ float d_cat[Bb * Dd * Nn];      // cat_img[b][dd][n]
__device__ float d_bound[1];

// ---------------- K0: q = Wq x + bq, qn = ||q||^2 ---------------------------
__global__ void __launch_bounds__(128) k_q(const float* __restrict__ x,
                                           const float* __restrict__ Wq,
                                           const float* __restrict__ bq) {
    __shared__ float sW[Hh * DHd * Dd];  // 4096 floats
    int tid = threadIdx.x;
    for (int i = tid; i < Hh * DHd * Dd; i += 128) sW[i] = Wq[i];
    __syncthreads();

    int b = blockIdx.y;
    int n = blockIdx.x * 128 + tid;
    const float* xb = x + b * Dd * Nn;

    float xv[Dd];
#pragma unroll
    for (int d = 0; d < Dd; d++) xv[d] = xb[d * Nn + n];

    for (int h = 0; h < Hh; h++) {
        float qn = 0.f;
        float* qo = d_q + ((size_t)(b * Hh + h) * Nn + n) * DHd;
#pragma unroll
        for (int k = 0; k < DHd; k++) {
            float acc = bq[h * DHd + k];
            const float* w = sW + (h * DHd + k) * Dd;
#pragma unroll
            for (int d = 0; d < Dd; d++) acc += w[d] * xv[d];
            qo[k] = acc;
            qn += acc * acc;
        }
        d_qn[(b * Hh + h) * Nn + n] = qn;
    }
}

// ---------------- K_A: A_h = WqR WqR^T / 4, WqR[i][j] = Wq[h].flat[i*16+j] --
__global__ void k_A(const float* __restrict__ Wq) {
    int h = blockIdx.x;
    __shared__ float sw[DHd * Dd];  // 1024 floats, viewed as WqR[64][16]
    for (int i = threadIdx.x; i < 1024; i += 256) sw[i] = Wq[h * 1024 + i];
    __syncthreads();
    for (int e = threadIdx.x; e < Dd * Dd; e += 256) {
        int i = e >> 6, i2 = e & 63;
        float acc = 0.f;
#pragma unroll
        for (int j = 0; j < DHd; j++) acc += sw[i * DHd + j] * sw[i2 * DHd + j];
        d_A[h * Dd * Dd + e] = acc * 0.25f;
    }
}

// ---------------- K_bound: Lipschitz bound (Lambert W in double) -----------
__global__ void k_bound(const float* __restrict__ Wq,
                        const float* __restrict__ Wv,
                        const float* __restrict__ Wo) {
    __shared__ float red[256];
    __shared__ float sq[Hh], sv[Hh];
    int tid = threadIdx.x;
    for (int h = 0; h < Hh; h++) {
        float a = 0.f;
        for (int i = tid; i < 1024; i += 256) { float w = Wq[h * 1024 + i]; a += w * w; }
        red[tid] = a; __syncthreads();
        for (int s = 128; s > 0; s >>= 1) { if (tid < s) red[tid] += red[tid + s]; __syncthreads(); }
        if (tid == 0) sq[h] = red[0];
        __syncthreads();
        a = 0.f;
        for (int i = tid; i < 1024; i += 256) { float w = Wv[h * 1024 + i]; a += w * w; }
        red[tid] = a; __syncthreads();
        for (int s = 128; s > 0; s >>= 1) { if (tid < s) red[tid] += red[tid + s]; __syncthreads(); }
        if (tid == 0) sv[h] = red[0];
        __syncthreads();
    }
    float a = 0.f;
    for (int i = tid; i < 4096; i += 256) { float w = Wo[i]; a += w * w; }
    red[tid] = a; __syncthreads();
    for (int s = 128; s > 0; s >>= 1) { if (tid < s) red[tid] += red[tid + s]; __syncthreads(); }
    if (tid == 0) {
        // phi = W0(N/e), Newton in double (matches numpy reference)
        double z = 2304.0 / 2.718281828459045;
        double w = log(z) - log(log(z));
        for (int it = 0; it < 30; it++) {
            double ew = exp(w);
            w = w - (w * ew - z) / (ew * (w + 1.0));
        }
        float phi = (float)w;
        float term = sqrtf(sq[0] * sv[0] + sq[1] * sv[1] + sq[2] * sv[2] + sq[3] * sv[3]);
        d_bound[0] = sqrtf(2304.f / 64.f) * (4.f * phi + 1.f) * term * sqrtf(red[0]);
    }
}

// ---------------- K1: flash-style softmax(P) @ x_r -------------------------
// logits l_m = 0.5 * (q_n . q_m) - 0.25 * qn_m   (row-const term cancels)
__global__ void __launch_bounds__(256) k_flash(const float* __restrict__ x) {
    int bh = blockIdx.y;
    int b  = bh >> 2;
    int n0 = blockIdx.x * 64;
    int tid = threadIdx.x;
    int ty = tid >> 4, tx = tid & 15;

    __shared__ __align__(16) float sQ[64][17];
    __shared__ __align__(16) float sK[64][17];
    __shared__ __align__(16) float sX[64][64];
    __shared__ __align__(16) float sP[64][65];
    __shared__ float sKn[64];

    const float* qbh = d_q + (size_t)bh * Nn * DHd;
    const float* qnb = d_qn + (size_t)bh * Nn;
    const float* xb  = x + (size_t)b * Dd * Nn;   // x_r[b][m][d] = xb[m*64+d]

    for (int i = tid; i < 64 * 16; i += 256) sQ[i >> 4][i & 15] = qbh[n0 * 16 + i];

    float mi[4], li[4], O[4][4];
#pragma unroll
    for (int i = 0; i < 4; i++) {
        mi[i] = -1e30f; li[i] = 0.f;
#pragma unroll
        for (int c = 0; c < 4; c++) O[i][c] = 0.f;
    }

    for (int t = 0; t < 36; t++) {
        int m0 = t * 64;
        __syncthreads();   // protect sK/sX/sP from previous iter consumers
        for (int i = tid; i < 64 * 16; i += 256) sK[i >> 4][i & 15] = qbh[m0 * 16 + i];
        if (tid < 64) sKn[tid] = qnb[m0 + tid];
        {
            const float4* src = (const float4*)(xb + m0 * 64);
            float4* dst = (float4*)(&sX[0][0]);
            for (int i = tid; i < 1024; i += 256) dst[i] = src[i];
        }
        __syncthreads();

        // gemm1: S[64x64] over dh=16
        float s[4][4];
#pragma unroll
        for (int i = 0; i < 4; i++)
#pragma unroll
            for (int j = 0; j < 4; j++) s[i][j] = 0.f;
#pragma unroll
        for (int kk = 0; kk < 16; kk++) {
            float qv[4], kv[4];
#pragma unroll
            for (int i = 0; i < 4; i++) qv[i] = sQ[ty + 16 * i][kk];
#pragma unroll
            for (int j = 0; j < 4; j++) kv[j] = sK[tx + 16 * j][kk];
#pragma unroll
            for (int i = 0; i < 4; i++)
#pragma unroll
                for (int j = 0; j < 4; j++) s[i][j] += qv[i] * kv[j];
        }
        float kn[4];
#pragma unroll
        for (int j = 0; j < 4; j++) kn[j] = sKn[tx + 16 * j];
#pragma unroll
        for (int i = 0; i < 4; i++)
#pragma unroll
            for (int j = 0; j < 4; j++) s[i][j] = 0.5f * s[i][j] - 0.25f * kn[j];

        // online softmax (state replicated across the 16 tx lanes of each ty)
#pragma unroll
        for (int i = 0; i < 4; i++) {
            float tm = fmaxf(fmaxf(s[i][0], s[i][1]), fmaxf(s[i][2], s[i][3]));
#pragma unroll
            for (int off = 8; off >= 1; off >>= 1)
                tm = fmaxf(tm, __shfl_xor_sync(0xffffffffu, tm, off));
            float mnew = fmaxf(mi[i], tm);
            float alpha = __expf(mi[i] - mnew);
            li[i] *= alpha;
#pragma unroll
            for (int c = 0; c < 4; c++) O[i][c] *= alpha;
            float rs = 0.f;
#pragma unroll
            for (int j = 0; j < 4; j++) {
                float p = __expf(s[i][j] - mnew);
                sP[ty + 16 * i][tx + 16 * j] = p;
                rs += p;
            }
#pragma unroll
            for (int off = 8; off >= 1; off >>= 1)
                rs += __shfl_xor_sync(0xffffffffu, rs, off);
            li[i] += rs;
            mi[i] = mnew;
        }
        __syncthreads();

        // gemm2: O += P @ X
#pragma unroll 4
        for (int mm = 0; mm < 64; mm++) {
            float pv[4];
#pragma unroll
            for (int i = 0; i < 4; i++) pv[i] = sP[ty + 16 * i][mm];
            float4 xv = *(const float4*)(&sX[mm][tx * 4]);
#pragma unroll
            for (int i = 0; i < 4; i++) {
                O[i][0] += pv[i] * xv.x;
                O[i][1] += pv[i] * xv.y;
                O[i][2] += pv[i] * xv.z;
                O[i][3] += pv[i] * xv.w;
            }
        }
    }

#pragma unroll
    for (int i = 0; i < 4; i++) {
        float inv = 1.f / li[i];
        float4 r;
        r.x = O[i][0] * inv; r.y = O[i][1] * inv;
        r.z = O[i][2] * inv; r.w = O[i][3] * inv;
        *(float4*)(&d_f[((size_t)bh * Nn + n0 + ty + 16 * i) * 64 + tx * 4]) = r;
    }
}

// ---------------- K2b: g = f @ A_h ------------------------------------------
__global__ void __launch_bounds__(256) k_gA() {
    int bh = blockIdx.y;
    int h = bh & 3;
    int n0 = blockIdx.x * 64;
    int tid = threadIdx.x, ty = tid >> 4, tx = tid & 15;
    __shared__ __align__(16) float sF[64][65];
    __shared__ __align__(16) float sA[64][64];
    for (int i = tid; i < 4096; i += 256) sA[i >> 6][i & 63] = d_A[h * 4096 + i];
    for (int i = tid; i < 4096; i += 256)
        sF[i >> 6][i & 63] = d_f[((size_t)bh * Nn + n0) * 64 + i];
    __syncthreads();
    float acc[4][4];
#pragma unroll
    for (int i = 0; i < 4; i++)
#pragma unroll
        for (int c = 0; c < 4; c++) acc[i][c] = 0.f;
#pragma unroll 4
    for (int dp = 0; dp < 64; dp++) {
        float fv[4];
#pragma unroll
        for (int i = 0; i < 4; i++) fv[i] = sF[ty + 16 * i][dp];
        float4 av = *(const float4*)(&sA[dp][tx * 4]);
#pragma unroll
        for (int i = 0; i < 4; i++) {
            acc[i][0] += fv[i] * av.x;
            acc[i][1] += fv[i] * av.y;
            acc[i][2] += fv[i] * av.z;
            acc[i][3] += fv[i] * av.w;
        }
    }
#pragma unroll
    for (int i = 0; i < 4; i++) {
        float4 r; r.x = acc[i][0]; r.y = acc[i][1]; r.z = acc[i][2]; r.w = acc[i][3];
        *(float4*)(&d_g[((size_t)bh * Nn + n0 + ty + 16 * i) * 64 + tx * 4]) = r;
    }
}

// ---------------- K2c: v[bh][k][vc] = Wv . f_img + bv -----------------------
// f_img[b,dd,vc] = g[bh, 36*dd + vc/64, vc%64]
__global__ void __launch_bounds__(256) k_v(const float* __restrict__ Wv,
                                           const float* __restrict__ bv) {
    int bh = blockIdx.y;
    int h = bh & 3;
    int vc = blockIdx.x * 256 + threadIdx.x;
    __shared__ float sw[DHd * Dd];
    for (int i = threadIdx.x; i < 1024; i += 256) sw[i] = Wv[h * 1024 + i];
    __syncthreads();
    int a = vc >> 6;
    int r = vc & 63;
    const float* gb = d_g + (size_t)bh * Nn * 64;
    float gv[64];
#pragma unroll
    for (int dd = 0; dd < 64; dd++) gv[dd] = gb[(36 * dd + a) * 64 + r];
#pragma unroll
    for (int k = 0; k < 16; k++) {
        float acc = bv[h * 16 + k];
        const float* w = sw + k * 64;
#pragma unroll
        for (int dd = 0; dd < 64; dd++) acc += w[dd] * gv[dd];
        d_v[((size_t)bh * 16 + k) * Nn + vc] = acc;
    }
}

// ---------------- K2c2: assemble cat_img[b][dd][n] ---------------------------
// cat_img[b,dd,n] = out_h(h = (n%64)/16)[b, 36*dd + n/64, (n%64)%16]
// out_h[b,np,kk] = v[bh, (np*16+kk)/2304, (np*16+kk)%2304]
__global__ void k_cat() {
    int idx = blockIdx.x * 256 + threadIdx.x;   // over B*D*N (exact multiple)
    int n = idx % Nn;
    int t = idx / Nn;
    int dd = t & 63;
    int b = t >> 6;
    int c = n & 63;
    int h = c >> 4;
    int kk = c & 15;
    int np = 36 * dd + (n >> 6);
    int vidx = np * 16 + kk;
    int vr = vidx / Nn;
    int vcol = vidx - vr * Nn;
    d_cat[idx] = d_v[((size_t)(b * Hh + h) * 16 + vr) * Nn + vcol];
}

// ---------------- K2d: out = Wo @ cat_img + bo; final = g*out/bound + x -----
__global__ void __launch_bounds__(256) k_out(const float* __restrict__ Wo,
                                             const float* __restrict__ bo,
                                             const float* __restrict__ gamma,
                                             const float* __restrict__ x,
                                             float* __restrict__ out) {
    int b = blockIdx.y;
    int n0 = blockIdx.x * 64;
    int tid = threadIdx.x, ty = tid >> 4, tx = tid & 15;
    __shared__ __align__(16) float sC[64][68];  // [dd][n], padded (16B-aligned rows)
    __shared__ float sW[64][64];                // [o][dd]
    for (int i = tid; i < 4096; i += 256)
        sC[i >> 6][i & 63] = d_cat[((size_t)b * 64 + (i >> 6)) * Nn + n0 + (i & 63)];
    for (int i = tid; i < 4096; i += 256) sW[i >> 6][i & 63] = Wo[i];
    __syncthreads();
    float acc[4][4];
#pragma unroll
    for (int i = 0; i < 4; i++)
#pragma unroll
        for (int c = 0; c < 4; c++) acc[i][c] = 0.f;
#pragma unroll 4
    for (int dd = 0; dd < 64; dd++) {
        float wv[4];
#pragma unroll
        for (int i = 0; i < 4; i++) wv[i] = sW[ty + 16 * i][dd];
        float4 cv = *(const float4*)(&sC[dd][tx * 4]);
#pragma unroll
        for (int i = 0; i < 4; i++) {
            acc[i][0] += wv[i] * cv.x;
            acc[i][1] += wv[i] * cv.y;
            acc[i][2] += wv[i] * cv.z;
            acc[i][3] += wv[i] * cv.w;
        }
    }
    float scale = gamma[0] / d_bound[0];
#pragma unroll
    for (int i = 0; i < 4; i++) {
        int o = ty + 16 * i;
        float bb = bo[o];
        size_t base = ((size_t)b * 64 + o) * Nn + n0 + tx * 4;
        float4 xin = *(const float4*)(&x[base]);
        float4 r;
        r.x = scale * (acc[i][0] + bb) + xin.x;
        r.y = scale * (acc[i][1] + bb) + xin.y;
        r.z = scale * (acc[i][2] + bb) + xin.z;
        r.w = scale * (acc[i][3] + bb) + xin.w;
        *(float4*)(&out[base]) = r;
    }
}

// ---------------- launch -----------------------------------------------------
extern "C" void kernel_launch(void* const* d_in, const int* in_sizes, int n_in,
                              void* d_out, int out_size) {
    const float* x     = (const float*)d_in[0];
    const float* Wq    = (const float*)d_in[1];
    const float* bq    = (const float*)d_in[2];
    const float* Wv    = (const float*)d_in[3];
    const float* bv    = (const float*)d_in[4];
    const float* Wo    = (const float*)d_in[5];
    const float* bo    = (const float*)d_in[6];
    const float* gamma = (const float*)d_in[7];
    float* out = (float*)d_out;

    k_q    <<<dim3(Nn / 128, Bb), 128>>>(x, Wq, bq);
    k_A    <<<Hh, 256>>>(Wq);
    k_bound<<<1, 256>>>(Wq, Wv, Wo);
    k_flash<<<dim3(Nn / 64, BHh), 256>>>(x);
    k_gA   <<<dim3(Nn / 64, BHh), 256>>>();
    k_v    <<<dim3(Nn / 256, BHh), 256>>>(Wv, bv);
    k_cat  <<<(Bb * Dd * Nn) / 256, 256>>>();
    k_out  <<<dim3(Nn / 64, Bb), 256>>>(Wo, bo, gamma, x, out);
}

// round 2
// speedup vs baseline: 1.9174x; 1.9174x over previous
#include <cuda_runtime.h>
#include <math.h>

#define Bb   4
#define Dd   64
#define Hh   4
#define DHd  16
#define Nn   2304
#define BHh  16   // B*heads

// ---------------- scratch (device globals; no allocation allowed) ----------
__device__ float d_q[BHh * Nn * DHd];      // q[bh][n][k]
__device__ float d_qn[BHh * Nn];           // ||q||^2 per (bh,n)
__device__ float d_z[BHh * Nn * DHd];      // Z = x_r @ R_h   [bh][m][c]
__device__ float d_u[BHh * Nn * DHd];      // U = softmax(P) @ Z
__device__ float d_g[BHh * Nn * Dd];       // g = U @ R^T / 4  (== f @ A)
__device__ float d_v[BHh * DHd * Nn];      // v[bh][k][vc]
__device__ float d_cat[Bb * Dd * Nn];      // cat_img[b][dd][n]
__device__ float d_bound[1];

// ---------------- K0: q = Wq x + bq, qn = ||q||^2 ---------------------------
__global__ void __launch_bounds__(128) k_q(const float* __restrict__ x,
                                           const float* __restrict__ Wq,
                                           const float* __restrict__ bq) {
    __shared__ float sW[Hh * DHd * Dd];  // 4096 floats
    int tid = threadIdx.x;
    for (int i = tid; i < Hh * DHd * Dd; i += 128) sW[i] = Wq[i];
    __syncthreads();

    int b = blockIdx.y;
    int n = blockIdx.x * 128 + tid;
    const float* xb = x + b * Dd * Nn;

    float xv[Dd];
#pragma unroll
    for (int d = 0; d < Dd; d++) xv[d] = xb[d * Nn + n];

    for (int h = 0; h < Hh; h++) {
        float qn = 0.f;
        float* qo = d_q + ((size_t)(b * Hh + h) * Nn + n) * DHd;
#pragma unroll
        for (int k = 0; k < DHd; k++) {
            float acc = bq[h * DHd + k];
            const float* w = sW + (h * DHd + k) * Dd;
#pragma unroll
            for (int d = 0; d < Dd; d++) acc += w[d] * xv[d];
            qo[k] = acc;
            qn += acc * acc;
        }
        d_qn[(b * Hh + h) * Nn + n] = qn;
    }
}

// ---------------- K_z: Z_h = x_r @ R_h  (R[dd][c] = Wq[h].flat[dd*16+c]) ----
__global__ void __launch_bounds__(256) k_z(const float* __restrict__ x,
                                           const float* __restrict__ Wq) {
    __shared__ float sR[Hh * Dd * DHd];   // 4096: sR[h*1024 + dd*16 + c]
    int tid = threadIdx.x;
    for (int i = tid; i < 4096; i += 256) sR[i] = Wq[i];
    __syncthreads();

    int b = blockIdx.y;
    int m = blockIdx.x * 256 + tid;
    const float* xr = x + (size_t)b * Dd * Nn + (size_t)m * Dd;  // x_r[b][m][:]

    float xv[Dd];
#pragma unroll
    for (int dc = 0; dc < 16; dc++) {
        float4 v = *(const float4*)(xr + dc * 4);
        xv[dc * 4 + 0] = v.x; xv[dc * 4 + 1] = v.y;
        xv[dc * 4 + 2] = v.z; xv[dc * 4 + 3] = v.w;
    }
    for (int h = 0; h < Hh; h++) {
        float acc[DHd];
#pragma unroll
        for (int c = 0; c < DHd; c++) acc[c] = 0.f;
#pragma unroll
        for (int d = 0; d < Dd; d++) {
            float xd = xv[d];
            const float4* rr = (const float4*)(sR + h * 1024 + d * 16);
#pragma unroll
            for (int cc = 0; cc < 4; cc++) {
                float4 rv = rr[cc];
                acc[cc * 4 + 0] += xd * rv.x;
                acc[cc * 4 + 1] += xd * rv.y;
                acc[cc * 4 + 2] += xd * rv.z;
                acc[cc * 4 + 3] += xd * rv.w;
            }
        }
        float* zo = d_z + ((size_t)(b * Hh + h) * Nn + m) * DHd;
#pragma unroll
        for (int cc = 0; cc < 4; cc++)
            *(float4*)(zo + cc * 4) = make_float4(acc[cc*4], acc[cc*4+1], acc[cc*4+2], acc[cc*4+3]);
    }
}

// ---------------- K_bound: Lipschitz bound (Lambert W in double) -----------
__global__ void k_bound(const float* __restrict__ Wq,
                        const float* __restrict__ Wv,
                        const float* __restrict__ Wo) {
    __shared__ float red[256];
    __shared__ float sq[Hh], sv[Hh];
    int tid = threadIdx.x;
    for (int h = 0; h < Hh; h++) {
        float a = 0.f;
        for (int i = tid; i < 1024; i += 256) { float w = Wq[h * 1024 + i]; a += w * w; }
        red[tid] = a; __syncthreads();
        for (int s = 128; s > 0; s >>= 1) { if (tid < s) red[tid] += red[tid + s]; __syncthreads(); }
        if (tid == 0) sq[h] = red[0];
        __syncthreads();
        a = 0.f;
        for (int i = tid; i < 1024; i += 256) { float w = Wv[h * 1024 + i]; a += w * w; }
        red[tid] = a; __syncthreads();
        for (int s = 128; s > 0; s >>= 1) { if (tid < s) red[tid] += red[tid + s]; __syncthreads(); }
        if (tid == 0) sv[h] = red[0];
        __syncthreads();
    }
    float a = 0.f;
    for (int i = tid; i < 4096; i += 256) { float w = Wo[i]; a += w * w; }
    red[tid] = a; __syncthreads();
    for (int s = 128; s > 0; s >>= 1) { if (tid < s) red[tid] += red[tid + s]; __syncthreads(); }
    if (tid == 0) {
        double z = 2304.0 / 2.718281828459045;
        double w = log(z) - log(log(z));
        for (int it = 0; it < 30; it++) {
            double ew = exp(w);
            w = w - (w * ew - z) / (ew * (w + 1.0));
        }
        float phi = (float)w;
        float term = sqrtf(sq[0] * sv[0] + sq[1] * sv[1] + sq[2] * sv[2] + sq[3] * sv[3]);
        d_bound[0] = sqrtf(2304.f / 64.f) * (4.f * phi + 1.f) * term * sqrtf(red[0]);
    }
}

// ---------------- K1: flash softmax, U = softmax(P) @ Z ---------------------
// logits l_m = 0.5 * (q_n . q_m) - 0.25 * qn_m   (row-const term cancels)
// thread (ty,tx): n-rows ty*4+i, m-cols tx*4+j; O[4][16] partial over own m's.
__global__ void __launch_bounds__(256, 2) k_flash() {
    int bh = blockIdx.y;
    int n0 = blockIdx.x * 64;
    int tid = threadIdx.x;
    int ty = tid >> 4, tx = tid & 15;

    __shared__ float sQt[16][64];
    __shared__ float sKt[16][64];
    __shared__ float sZt[16][64];
    __shared__ float sKn[64];

    const float* qbh = d_q + (size_t)bh * Nn * DHd;
    const float* zbh = d_z + (size_t)bh * Nn * DHd;
    const float* qnb = d_qn + (size_t)bh * Nn;

    // load Q tile transposed (k-major)
    {
        int m = tid & 63, kc = tid >> 6;
        float4 v = *(const float4*)(qbh + (size_t)(n0 + m) * 16 + kc * 4);
        sQt[kc * 4 + 0][m] = v.x; sQt[kc * 4 + 1][m] = v.y;
        sQt[kc * 4 + 2][m] = v.z; sQt[kc * 4 + 3][m] = v.w;
    }

    float O[4][16];
    float mi[4], li[4];
#pragma unroll
    for (int i = 0; i < 4; i++) {
        mi[i] = -1e30f; li[i] = 0.f;
#pragma unroll
        for (int c = 0; c < 16; c++) O[i][c] = 0.f;
    }

    for (int t = 0; t < 36; t++) {
        int m0 = t * 64;
        __syncthreads();
        {
            int m = tid & 63, kc = tid >> 6;
            float4 v = *(const float4*)(qbh + (size_t)(m0 + m) * 16 + kc * 4);
            sKt[kc * 4 + 0][m] = v.x; sKt[kc * 4 + 1][m] = v.y;
            sKt[kc * 4 + 2][m] = v.z; sKt[kc * 4 + 3][m] = v.w;
            float4 z = *(const float4*)(zbh + (size_t)(m0 + m) * 16 + kc * 4);
            sZt[kc * 4 + 0][m] = z.x; sZt[kc * 4 + 1][m] = z.y;
            sZt[kc * 4 + 2][m] = z.z; sZt[kc * 4 + 3][m] = z.w;
            if (tid < 64) sKn[tid] = qnb[m0 + tid];
        }
        __syncthreads();

        // gemm1: s[4][4] over dh=16
        float s[4][4];
#pragma unroll
        for (int i = 0; i < 4; i++)
#pragma unroll
            for (int j = 0; j < 4; j++) s[i][j] = 0.f;
#pragma unroll
        for (int kk = 0; kk < 16; kk++) {
            float4 qv = *(const float4*)(&sQt[kk][ty * 4]);
            float4 kv = *(const float4*)(&sKt[kk][tx * 4]);
            float q[4] = {qv.x, qv.y, qv.z, qv.w};
            float kvv[4] = {kv.x, kv.y, kv.z, kv.w};
#pragma unroll
            for (int i = 0; i < 4; i++)
#pragma unroll
                for (int j = 0; j < 4; j++) s[i][j] += q[i] * kvv[j];
        }
        float4 knv = *(const float4*)(&sKn[tx * 4]);
        float kn[4] = {knv.x, knv.y, knv.z, knv.w};
#pragma unroll
        for (int i = 0; i < 4; i++)
#pragma unroll
            for (int j = 0; j < 4; j++) s[i][j] = 0.5f * s[i][j] - 0.25f * kn[j];

        // online softmax; p kept in registers (reuse s)
#pragma unroll
        for (int i = 0; i < 4; i++) {
            float tm = fmaxf(fmaxf(s[i][0], s[i][1]), fmaxf(s[i][2], s[i][3]));
#pragma unroll
            for (int off = 8; off >= 1; off >>= 1)
                tm = fmaxf(tm, __shfl_xor_sync(0xffffffffu, tm, off));
            float mnew = fmaxf(mi[i], tm);
            float alpha = __expf(mi[i] - mnew);
            li[i] *= alpha;
#pragma unroll
            for (int c = 0; c < 16; c++) O[i][c] *= alpha;
            float rs = 0.f;
#pragma unroll
            for (int j = 0; j < 4; j++) {
                float p = __expf(s[i][j] - mnew);
                s[i][j] = p;
                rs += p;
            }
#pragma unroll
            for (int off = 8; off >= 1; off >>= 1)
                rs += __shfl_xor_sync(0xffffffffu, rs, off);
            li[i] += rs;
            mi[i] = mnew;
        }

        // gemm2: O[i][c] += p[i][j] * Z[m_j][c]  (own 4 m's only)
#pragma unroll
        for (int c = 0; c < 16; c++) {
            float4 zv = *(const float4*)(&sZt[c][tx * 4]);
            float zz[4] = {zv.x, zv.y, zv.z, zv.w};
#pragma unroll
            for (int i = 0; i < 4; i++) {
                O[i][c] += s[i][0] * zz[0] + s[i][1] * zz[1]
                         + s[i][2] * zz[2] + s[i][3] * zz[3];
            }
        }
    }

    // reduce O over the 16 tx lanes (m-partitions)
#pragma unroll
    for (int off = 8; off >= 1; off >>= 1) {
#pragma unroll
        for (int i = 0; i < 4; i++)
#pragma unroll
            for (int c = 0; c < 16; c++)
                O[i][c] += __shfl_xor_sync(0xffffffffu, O[i][c], off);
    }
    if (tx == 0) {
#pragma unroll
        for (int i = 0; i < 4; i++) {
            float inv = 1.f / li[i];
            float* uo = d_u + ((size_t)bh * Nn + n0 + ty * 4 + i) * DHd;
#pragma unroll
            for (int cc = 0; cc < 4; cc++)
                *(float4*)(uo + cc * 4) = make_float4(O[i][cc*4] * inv, O[i][cc*4+1] * inv,
                                                      O[i][cc*4+2] * inv, O[i][cc*4+3] * inv);
        }
    }
}

// ---------------- K_g: g = U @ R^T / 4  (g[n][dd] = 0.25 sum_c U[n][c] R[dd][c])
__global__ void __launch_bounds__(256) k_g(const float* __restrict__ Wq) {
    int bh = blockIdx.y;
    int h = bh & 3;
    int n0 = blockIdx.x * 64;
    int tid = threadIdx.x, ty = tid >> 4, tx = tid & 15;

    __shared__ float sUt[16][64];
    __shared__ float sRt[16][64];
    {
        int n = tid & 63, cg = tid >> 6;
        float4 v = *(const float4*)(d_u + ((size_t)bh * Nn + n0 + n) * DHd + cg * 4);
        sUt[cg * 4 + 0][n] = v.x; sUt[cg * 4 + 1][n] = v.y;
        sUt[cg * 4 + 2][n] = v.z; sUt[cg * 4 + 3][n] = v.w;
        int dd = tid & 63;
        float4 r = *(const float4*)(Wq + h * 1024 + dd * 16 + cg * 4);
        sRt[cg * 4 + 0][dd] = r.x; sRt[cg * 4 + 1][dd] = r.y;
        sRt[cg * 4 + 2][dd] = r.z; sRt[cg * 4 + 3][dd] = r.w;
    }
    __syncthreads();

    float acc[4][4];
#pragma unroll
    for (int i = 0; i < 4; i++)
#pragma unroll
        for (int j = 0; j < 4; j++) acc[i][j] = 0.f;
#pragma unroll
    for (int c = 0; c < 16; c++) {
        float4 uv = *(const float4*)(&sUt[c][ty * 4]);
        float4 rv = *(const float4*)(&sRt[c][tx * 4]);
        float u[4] = {uv.x, uv.y, uv.z, uv.w};
        float r[4] = {rv.x, rv.y, rv.z, rv.w};
#pragma unroll
        for (int i = 0; i < 4; i++)
#pragma unroll
            for (int j = 0; j < 4; j++) acc[i][j] += u[i] * r[j];
    }
#pragma unroll
    for (int i = 0; i < 4; i++) {
        float4 w = make_float4(acc[i][0] * 0.25f, acc[i][1] * 0.25f,
                               acc[i][2] * 0.25f, acc[i][3] * 0.25f);
        *(float4*)(d_g + ((size_t)bh * Nn + n0 + ty * 4 + i) * 64 + tx * 4) = w;
    }
}

// ---------------- K2c: v[bh][k][vc] = Wv . f_img + bv -----------------------
// f_img[b,dd,vc] = g[bh, 36*dd + vc/64, vc%64]
__global__ void __launch_bounds__(256) k_v(const float* __restrict__ Wv,
                                           const float* __restrict__ bv) {
    int bh = blockIdx.y;
    int h = bh & 3;
    int vc = blockIdx.x * 256 + threadIdx.x;
    __shared__ float sw[DHd * Dd];
    for (int i = threadIdx.x; i < 1024; i += 256) sw[i] = Wv[h * 1024 + i];
    __syncthreads();
    int a = vc >> 6;
    int r = vc & 63;
    const float* gb = d_g + (size_t)bh * Nn * 64;
    float gv[64];
#pragma unroll
    for (int dd = 0; dd < 64; dd++) gv[dd] = gb[(36 * dd + a) * 64 + r];
#pragma unroll
    for (int k = 0; k < 16; k++) {
        float acc = bv[h * 16 + k];
        const float* w = sw + k * 64;
#pragma unroll
        for (int dd = 0; dd < 64; dd++) acc += w[dd] * gv[dd];
        d_v[((size_t)bh * 16 + k) * Nn + vc] = acc;
    }
}

// ---------------- K2c2: assemble cat_img[b][dd][n] ---------------------------
__global__ void k_cat() {
    int idx = blockIdx.x * 256 + threadIdx.x;   // over B*D*N
    int n = idx % Nn;
    int t = idx / Nn;
    int dd = t & 63;
    int b = t >> 6;
    int c = n & 63;
    int h = c >> 4;
    int kk = c & 15;
    int np = 36 * dd + (n >> 6);
    int vidx = np * 16 + kk;
    int vr = vidx / Nn;
    int vcol = vidx - vr * Nn;
    d_cat[idx] = d_v[((size_t)(b * Hh + h) * 16 + vr) * Nn + vcol];
}

// ---------------- K2d: out = Wo @ cat_img + bo; final = g*out/bound + x -----
__global__ void __launch_bounds__(256) k_out(const float* __restrict__ Wo,
                                             const float* __restrict__ bo,
                                             const float* __restrict__ gamma,
                                             const float* __restrict__ x,
                                             float* __restrict__ out) {
    int b = blockIdx.y;
    int n0 = blockIdx.x * 64;
    int tid = threadIdx.x, ty = tid >> 4, tx = tid & 15;
    __shared__ __align__(16) float sC[64][68];
    __shared__ float sW[64][64];
    for (int i = tid; i < 4096; i += 256)
        sC[i >> 6][i & 63] = d_cat[((size_t)b * 64 + (i >> 6)) * Nn + n0 + (i & 63)];
    for (int i = tid; i < 4096; i += 256) sW[i >> 6][i & 63] = Wo[i];
    __syncthreads();
    float acc[4][4];
#pragma unroll
    for (int i = 0; i < 4; i++)
#pragma unroll
        for (int c = 0; c < 4; c++) acc[i][c] = 0.f;
#pragma unroll 4
    for (int dd = 0; dd < 64; dd++) {
        float wv[4];
#pragma unroll
        for (int i = 0; i < 4; i++) wv[i] = sW[ty + 16 * i][dd];
        float4 cv = *(const float4*)(&sC[dd][tx * 4]);
#pragma unroll
        for (int i = 0; i < 4; i++) {
            acc[i][0] += wv[i] * cv.x;
            acc[i][1] += wv[i] * cv.y;
            acc[i][2] += wv[i] * cv.z;
            acc[i][3] += wv[i] * cv.w;
        }
    }
    float scale = gamma[0] / d_bound[0];
#pragma unroll
    for (int i = 0; i < 4; i++) {
        int o = ty + 16 * i;
        float bb = bo[o];
        size_t base = ((size_t)b * 64 + o) * Nn + n0 + tx * 4;
        float4 xin = *(const float4*)(&x[base]);
        float4 r;
        r.x = scale * (acc[i][0] + bb) + xin.x;
        r.y = scale * (acc[i][1] + bb) + xin.y;
        r.z = scale * (acc[i][2] + bb) + xin.z;
        r.w = scale * (acc[i][3] + bb) + xin.w;
        *(float4*)(&out[base]) = r;
    }
}

// ---------------- launch -----------------------------------------------------
extern "C" void kernel_launch(void* const* d_in, const int* in_sizes, int n_in,
                              void* d_out, int out_size) {
    const float* x     = (const float*)d_in[0];
    const float* Wq    = (const float*)d_in[1];
    const float* bq    = (const float*)d_in[2];
    const float* Wv    = (const float*)d_in[3];
    const float* bv    = (const float*)d_in[4];
    const float* Wo    = (const float*)d_in[5];
    const float* bo    = (const float*)d_in[6];
    const float* gamma = (const float*)d_in[7];
    float* out = (float*)d_out;

    k_q    <<<dim3(Nn / 128, Bb), 128>>>(x, Wq, bq);
    k_z    <<<dim3(Nn / 256, Bb), 256>>>(x, Wq);
    k_bound<<<1, 256>>>(Wq, Wv, Wo);
    k_flash<<<dim3(Nn / 64, BHh), 256>>>();
    k_g    <<<dim3(Nn / 64, BHh), 256>>>(Wq);
    k_v    <<<dim3(Nn / 256, BHh), 256>>>(Wv, bv);
    k_cat  <<<(Bb * Dd * Nn) / 256, 256>>>();
    k_out  <<<dim3(Nn / 64, Bb), 256>>>(Wo, bo, gamma, x, out);
}

// round 3
// speedup vs baseline: 2.4092x; 1.2565x over previous
#include <cuda_runtime.h>
#include <math.h>

#define Bb   4
#define Dd   64
#define Hh   4
#define DHd  16
#define Nn   2304
#define BHh  16   // B*heads

#define LOG2E      1.4426950408889634f
#define HALF_LOG2E 0.7213475204444817f

// ---------------- scratch (device globals) ----------------------------------
__device__ float d_qt[BHh * DHd * Nn];     // q transposed: [bh][k][n]
__device__ float d_qn[BHh * Nn];           // 0.25*log2e*||q||^2
__device__ float d_zt[BHh * DHd * Nn];     // Z transposed: [bh][c][m]
__device__ float d_u[BHh * Nn * DHd];      // U = softmax(P) @ Z   [bh][n][c]
__device__ float d_g[BHh * Nn * Dd];       // g = U @ R^T / 4
__device__ float d_v[BHh * DHd * Nn];      // v[bh][k][vc]
__device__ float d_bound[1];

__device__ __forceinline__ float ex2(float a) {
    float r;
    asm("ex2.approx.ftz.f32 %0, %1;" : "=f"(r) : "f"(a));
    return r;
}

// ---------------- K0: q = Wq x + bq (transposed out), qn scaled -------------
__global__ void __launch_bounds__(128) k_q(const float* __restrict__ x,
                                           const float* __restrict__ Wq,
                                           const float* __restrict__ bq) {
    __shared__ float sW[Hh * DHd * Dd];
    int tid = threadIdx.x;
    for (int i = tid; i < Hh * DHd * Dd; i += 128) sW[i] = Wq[i];
    __syncthreads();

    int b = blockIdx.y;
    int n = blockIdx.x * 128 + tid;
    const float* xb = x + b * Dd * Nn;

    float xv[Dd];
#pragma unroll
    for (int d = 0; d < Dd; d++) xv[d] = xb[d * Nn + n];

    for (int h = 0; h < Hh; h++) {
        int bh = b * Hh + h;
        float qn = 0.f;
#pragma unroll
        for (int k = 0; k < DHd; k++) {
            float acc = bq[h * DHd + k];
            const float* w = sW + (h * DHd + k) * Dd;
#pragma unroll
            for (int d = 0; d < Dd; d++) acc += w[d] * xv[d];
            d_qt[((size_t)bh * DHd + k) * Nn + n] = acc;
            qn += acc * acc;
        }
        d_qn[(size_t)bh * Nn + n] = qn * (0.25f * LOG2E);
    }
}

// ---------------- K_z: Z_h = x_r @ R_h (transposed out) ---------------------
__global__ void __launch_bounds__(256) k_z(const float* __restrict__ x,
                                           const float* __restrict__ Wq) {
    __shared__ float sR[Hh * Dd * DHd];
    int tid = threadIdx.x;
    for (int i = tid; i < 4096; i += 256) sR[i] = Wq[i];
    __syncthreads();

    int b = blockIdx.y;
    int m = blockIdx.x * 256 + tid;
    const float* xr = x + (size_t)b * Dd * Nn + (size_t)m * Dd;

    float xv[Dd];
#pragma unroll
    for (int dc = 0; dc < 16; dc++) {
        float4 v = *(const float4*)(xr + dc * 4);
        xv[dc * 4 + 0] = v.x; xv[dc * 4 + 1] = v.y;
        xv[dc * 4 + 2] = v.z; xv[dc * 4 + 3] = v.w;
    }
    for (int h = 0; h < Hh; h++) {
        int bh = b * Hh + h;
        float acc[DHd];
#pragma unroll
        for (int c = 0; c < DHd; c++) acc[c] = 0.f;
#pragma unroll
        for (int d = 0; d < Dd; d++) {
            float xd = xv[d];
            const float4* rr = (const float4*)(sR + h * 1024 + d * 16);
#pragma unroll
            for (int cc = 0; cc < 4; cc++) {
                float4 rv = rr[cc];
                acc[cc * 4 + 0] += xd * rv.x;
                acc[cc * 4 + 1] += xd * rv.y;
                acc[cc * 4 + 2] += xd * rv.z;
                acc[cc * 4 + 3] += xd * rv.w;
            }
        }
#pragma unroll
        for (int c = 0; c < DHd; c++)
            d_zt[((size_t)bh * DHd + c) * Nn + m] = acc[c];
    }
}

// ---------------- K_bound ----------------------------------------------------
__global__ void k_bound(const float* __restrict__ Wq,
                        const float* __restrict__ Wv,
                        const float* __restrict__ Wo) {
    __shared__ float red[256];
    __shared__ float sq[Hh], sv[Hh];
    int tid = threadIdx.x;
    for (int h = 0; h < Hh; h++) {
        float a = 0.f;
        for (int i = tid; i < 1024; i += 256) { float w = Wq[h * 1024 + i]; a += w * w; }
        red[tid] = a; __syncthreads();
        for (int s = 128; s > 0; s >>= 1) { if (tid < s) red[tid] += red[tid + s]; __syncthreads(); }
        if (tid == 0) sq[h] = red[0];
        __syncthreads();
        a = 0.f;
        for (int i = tid; i < 1024; i += 256) { float w = Wv[h * 1024 + i]; a += w * w; }
        red[tid] = a; __syncthreads();
        for (int s = 128; s > 0; s >>= 1) { if (tid < s) red[tid] += red[tid + s]; __syncthreads(); }
        if (tid == 0) sv[h] = red[0];
        __syncthreads();
    }
    float a = 0.f;
    for (int i = tid; i < 4096; i += 256) { float w = Wo[i]; a += w * w; }
    red[tid] = a; __syncthreads();
    for (int s = 128; s > 0; s >>= 1) { if (tid < s) red[tid] += red[tid + s]; __syncthreads(); }
    if (tid == 0) {
        double z = 2304.0 / 2.718281828459045;
        double w = log(z) - log(log(z));
        for (int it = 0; it < 30; it++) {
            double ew = exp(w);
            w = w - (w * ew - z) / (ew * (w + 1.0));
        }
        float phi = (float)w;
        float term = sqrtf(sq[0] * sv[0] + sq[1] * sv[1] + sq[2] * sv[2] + sq[3] * sv[3]);
        d_bound[0] = sqrtf(2304.f / 64.f) * (4.f * phi + 1.f) * term * sqrtf(red[0]);
    }
}

// ---------------- K1: flash, p = exp2(0.5log2e q.k - qnl_n - qnl_m) <= 1 ----
__global__ void __launch_bounds__(256, 2) k_flash() {
    int bh = blockIdx.y;
    int n0 = blockIdx.x * 64;
    int tid = threadIdx.x;
    int ty = tid >> 4, tx = tid & 15;

    __shared__ float sQt[16][64];
    __shared__ float sKt[16][64];
    __shared__ float sZt[16][64];
    __shared__ float sKn[64];

    const float* qtb = d_qt + (size_t)bh * DHd * Nn;
    const float* ztb = d_zt + (size_t)bh * DHd * Nn;
    const float* qnb = d_qn + (size_t)bh * Nn;

    int lrow = tid >> 4;          // 0..15 (k index)
    int lcol = (tid & 15) * 4;    // 0..60 (col within tile)

    // Q tile, pre-scaled by 0.5*log2e
    {
        float4 v = *(const float4*)(qtb + (size_t)lrow * Nn + n0 + lcol);
        float4 w = make_float4(v.x * HALF_LOG2E, v.y * HALF_LOG2E,
                               v.z * HALF_LOG2E, v.w * HALF_LOG2E);
        *(float4*)(&sQt[lrow][lcol]) = w;
    }
    float qnl[4];
    {
        float4 v = *(const float4*)(qnb + n0 + ty * 4);
        qnl[0] = v.x; qnl[1] = v.y; qnl[2] = v.z; qnl[3] = v.w;
    }

    float O[4][16];
    float li[4];
#pragma unroll
    for (int i = 0; i < 4; i++) {
        li[i] = 0.f;
#pragma unroll
        for (int c = 0; c < 16; c++) O[i][c] = 0.f;
    }

    // prefetch tile 0
    float4 pK = *(const float4*)(qtb + (size_t)lrow * Nn + lcol);
    float4 pZ = *(const float4*)(ztb + (size_t)lrow * Nn + lcol);
    float pN = (tid < 64) ? qnb[tid] : 0.f;

    for (int t = 0; t < 36; t++) {
        __syncthreads();
        *(float4*)(&sKt[lrow][lcol]) = pK;
        *(float4*)(&sZt[lrow][lcol]) = pZ;
        if (tid < 64) sKn[tid] = pN;
        if (t < 35) {
            int m0 = (t + 1) * 64;
            pK = *(const float4*)(qtb + (size_t)lrow * Nn + m0 + lcol);
            pZ = *(const float4*)(ztb + (size_t)lrow * Nn + m0 + lcol);
            if (tid < 64) pN = qnb[m0 + tid];
        }
        __syncthreads();

        // gemm1: s[4][4] over dh=16 (Q side pre-scaled)
        float s[4][4];
#pragma unroll
        for (int i = 0; i < 4; i++)
#pragma unroll
            for (int j = 0; j < 4; j++) s[i][j] = 0.f;
#pragma unroll
        for (int kk = 0; kk < 16; kk++) {
            float4 qv = *(const float4*)(&sQt[kk][ty * 4]);
            float4 kv = *(const float4*)(&sKt[kk][tx * 4]);
            float q[4] = {qv.x, qv.y, qv.z, qv.w};
            float k4[4] = {kv.x, kv.y, kv.z, kv.w};
#pragma unroll
            for (int i = 0; i < 4; i++)
#pragma unroll
                for (int j = 0; j < 4; j++) s[i][j] += q[i] * k4[j];
        }
        // p = exp2(s - qnl_i - kn_j); accumulate li; keep p in s
        float4 knv = *(const float4*)(&sKn[tx * 4]);
        float kn[4] = {knv.x, knv.y, knv.z, knv.w};
#pragma unroll
        for (int i = 0; i < 4; i++) {
#pragma unroll
            for (int j = 0; j < 4; j++) {
                float p = ex2(s[i][j] - qnl[i] - kn[j]);
                s[i][j] = p;
                li[i] += p;
            }
        }
        // gemm2: O[i][c] += p[i][j] * Z[c][m_j]
#pragma unroll
        for (int c = 0; c < 16; c++) {
            float4 zv = *(const float4*)(&sZt[c][tx * 4]);
#pragma unroll
            for (int i = 0; i < 4; i++) {
                O[i][c] += s[i][0] * zv.x + s[i][1] * zv.y
                         + s[i][2] * zv.z + s[i][3] * zv.w;
            }
        }
    }

    // reduce O, li over the 16 tx lanes
#pragma unroll
    for (int off = 8; off >= 1; off >>= 1) {
#pragma unroll
        for (int i = 0; i < 4; i++) {
            li[i] += __shfl_xor_sync(0xffffffffu, li[i], off);
#pragma unroll
            for (int c = 0; c < 16; c++)
                O[i][c] += __shfl_xor_sync(0xffffffffu, O[i][c], off);
        }
    }
    if (tx == 0) {
#pragma unroll
        for (int i = 0; i < 4; i++) {
            float inv = 1.f / li[i];
            float* uo = d_u + ((size_t)bh * Nn + n0 + ty * 4 + i) * DHd;
#pragma unroll
            for (int cc = 0; cc < 4; cc++)
                *(float4*)(uo + cc * 4) = make_float4(O[i][cc*4] * inv, O[i][cc*4+1] * inv,
                                                      O[i][cc*4+2] * inv, O[i][cc*4+3] * inv);
        }
    }
}

// ---------------- K_g: g = U @ R^T / 4 --------------------------------------
__global__ void __launch_bounds__(256) k_g(const float* __restrict__ Wq) {
    int bh = blockIdx.y;
    int h = bh & 3;
    int n0 = blockIdx.x * 64;
    int tid = threadIdx.x, ty = tid >> 4, tx = tid & 15;

    __shared__ float sUt[16][64];
    __shared__ float sRt[16][64];
    {
        int n = tid & 63, cg = tid >> 6;
        float4 v = *(const float4*)(d_u + ((size_t)bh * Nn + n0 + n) * DHd + cg * 4);
        sUt[cg * 4 + 0][n] = v.x; sUt[cg * 4 + 1][n] = v.y;
        sUt[cg * 4 + 2][n] = v.z; sUt[cg * 4 + 3][n] = v.w;
        int dd = tid & 63;
        float4 r = *(const float4*)(Wq + h * 1024 + dd * 16 + cg * 4);
        sRt[cg * 4 + 0][dd] = r.x; sRt[cg * 4 + 1][dd] = r.y;
        sRt[cg * 4 + 2][dd] = r.z; sRt[cg * 4 + 3][dd] = r.w;
    }
    __syncthreads();

    float acc[4][4];
#pragma unroll
    for (int i = 0; i < 4; i++)
#pragma unroll
        for (int j = 0; j < 4; j++) acc[i][j] = 0.f;
#pragma unroll
    for (int c = 0; c < 16; c++) {
        float4 uv = *(const float4*)(&sUt[c][ty * 4]);
        float4 rv = *(const float4*)(&sRt[c][tx * 4]);
        float u[4] = {uv.x, uv.y, uv.z, uv.w};
        float r[4] = {rv.x, rv.y, rv.z, rv.w};
#pragma unroll
        for (int i = 0; i < 4; i++)
#pragma unroll
            for (int j = 0; j < 4; j++) acc[i][j] += u[i] * r[j];
    }
#pragma unroll
    for (int i = 0; i < 4; i++) {
        float4 w = make_float4(acc[i][0] * 0.25f, acc[i][1] * 0.25f,
                               acc[i][2] * 0.25f, acc[i][3] * 0.25f);
        *(float4*)(d_g + ((size_t)bh * Nn + n0 + ty * 4 + i) * 64 + tx * 4) = w;
    }
}

// ---------------- K_v: v[bh][k][vc] = Wv . f_img + bv -----------------------
__global__ void __launch_bounds__(256) k_v(const float* __restrict__ Wv,
                                           const float* __restrict__ bv) {
    int bh = blockIdx.y;
    int h = bh & 3;
    int vc = blockIdx.x * 256 + threadIdx.x;
    __shared__ float sw[DHd * Dd];
    for (int i = threadIdx.x; i < 1024; i += 256) sw[i] = Wv[h * 1024 + i];
    __syncthreads();
    int a = vc >> 6;
    int r = vc & 63;
    const float* gb = d_g + (size_t)bh * Nn * 64;
    float gv[64];
#pragma unroll
    for (int dd = 0; dd < 64; dd++) gv[dd] = gb[(36 * dd + a) * 64 + r];
#pragma unroll
    for (int k = 0; k < 16; k++) {
        float acc = bv[h * 16 + k];
        const float* w = sw + k * 64;
#pragma unroll
        for (int dd = 0; dd < 64; dd++) acc += w[dd] * gv[dd];
        d_v[((size_t)bh * 16 + k) * Nn + vc] = acc;
    }
}

// ---------------- K_out: cat gather + Wo gemm + residual --------------------
__global__ void __launch_bounds__(256) k_out(const float* __restrict__ Wo,
                                             const float* __restrict__ bo,
                                             const float* __restrict__ gamma,
                                             const float* __restrict__ x,
                                             float* __restrict__ out) {
    int b = blockIdx.y;
    int n0 = blockIdx.x * 64;
    int a = n0 >> 6;
    int tid = threadIdx.x, ty = tid >> 4, tx = tid & 15;
    __shared__ __align__(16) float sC[64][68];
    __shared__ float sW[64][64];
    for (int i = tid; i < 4096; i += 256) {
        int dd = i >> 6, j = i & 63;
        int h = j >> 4, kk = j & 15;
        int vidx = (36 * dd + a) * 16 + kk;
        int vr = vidx / Nn;
        int vcol = vidx - vr * Nn;
        sC[dd][j] = d_v[((size_t)(b * Hh + h) * 16 + vr) * Nn + vcol];
    }
    for (int i = tid; i < 4096; i += 256) sW[i >> 6][i & 63] = Wo[i];
    __syncthreads();
    float acc[4][4];
#pragma unroll
    for (int i = 0; i < 4; i++)
#pragma unroll
        for (int c = 0; c < 4; c++) acc[i][c] = 0.f;
#pragma unroll 4
    for (int dd = 0; dd < 64; dd++) {
        float wv[4];
#pragma unroll
        for (int i = 0; i < 4; i++) wv[i] = sW[ty + 16 * i][dd];
        float4 cv = *(const float4*)(&sC[dd][tx * 4]);
#pragma unroll
        for (int i = 0; i < 4; i++) {
            acc[i][0] += wv[i] * cv.x;
            acc[i][1] += wv[i] * cv.y;
            acc[i][2] += wv[i] * cv.z;
            acc[i][3] += wv[i] * cv.w;
        }
    }
    float scale = gamma[0] / d_bound[0];
#pragma unroll
    for (int i = 0; i < 4; i++) {
        int o = ty + 16 * i;
        float bb = bo[o];
        size_t base = ((size_t)b * 64 + o) * Nn + n0 + tx * 4;
        float4 xin = *(const float4*)(&x[base]);
        float4 r;
        r.x = scale * (acc[i][0] + bb) + xin.x;
        r.y = scale * (acc[i][1] + bb) + xin.y;
        r.z = scale * (acc[i][2] + bb) + xin.z;
        r.w = scale * (acc[i][3] + bb) + xin.w;
        *(float4*)(&out[base]) = r;
    }
}

// ---------------- launch -----------------------------------------------------
extern "C" void kernel_launch(void* const* d_in, const int* in_sizes, int n_in,
                              void* d_out, int out_size) {
    const float* x     = (const float*)d_in[0];
    const float* Wq    = (const float*)d_in[1];
    const float* bq    = (const float*)d_in[2];
    const float* Wv    = (const float*)d_in[3];
    const float* bv    = (const float*)d_in[4];
    const float* Wo    = (const float*)d_in[5];
    const float* bo    = (const float*)d_in[6];
    const float* gamma = (const float*)d_in[7];
    float* out = (float*)d_out;

    k_q    <<<dim3(Nn / 128, Bb), 128>>>(x, Wq, bq);
    k_z    <<<dim3(Nn / 256, Bb), 256>>>(x, Wq);
    k_bound<<<1, 256>>>(Wq, Wv, Wo);
    k_flash<<<dim3(Nn / 64, BHh), 256>>>();
    k_g    <<<dim3(Nn / 64, BHh), 256>>>(Wq);
    k_v    <<<dim3(Nn / 256, BHh), 256>>>(Wv, bv);
    k_out  <<<dim3(Nn / 64, Bb), 256>>>(Wo, bo, gamma, x, out);
}